// round 12
// baseline (speedup 1.0000x reference)
#include <cuda_runtime.h>
#include <cuda_bf16.h>
#include <stdint.h>
#include <math.h>

#define BATCH 2
#define NTOK  2048
#define CDIM  768
#define HEADS 12
#define DHEAD 64
#define HALF  64
#define SCALE 0.125f  /* 64^-0.5 */

// ---------------- scratch (device globals; no allocations allowed) ----------
// bf16 hi/lo split operand buffers. Only referenced from DEVICE code.
__device__ __align__(16) __nv_bfloat16 g_xh[(size_t)BATCH * NTOK * CDIM];
__device__ __align__(16) __nv_bfloat16 g_xl[(size_t)BATCH * NTOK * CDIM];
__device__ __align__(16) __nv_bfloat16 g_wqh[(size_t)3 * CDIM * CDIM];
__device__ __align__(16) __nv_bfloat16 g_wql[(size_t)3 * CDIM * CDIM];
__device__ __align__(16) __nv_bfloat16 g_wph[(size_t)CDIM * CDIM];
__device__ __align__(16) __nv_bfloat16 g_wpl[(size_t)CDIM * CDIM];
__device__ __align__(16) __nv_bfloat16 g_Qh[(size_t)BATCH * HEADS * NTOK * DHEAD];
__device__ __align__(16) __nv_bfloat16 g_Ql[(size_t)BATCH * HEADS * NTOK * DHEAD];
__device__ __align__(16) __nv_bfloat16 g_Kh[(size_t)BATCH * HEADS * NTOK * DHEAD];
__device__ __align__(16) __nv_bfloat16 g_Kl[(size_t)BATCH * HEADS * NTOK * DHEAD];
__device__ __align__(16) __nv_bfloat16 g_Vh[(size_t)BATCH * HEADS * NTOK * DHEAD];
__device__ __align__(16) __nv_bfloat16 g_Vl[(size_t)BATCH * HEADS * NTOK * DHEAD];
__device__ __align__(16) __nv_bfloat16 g_Oh[(size_t)BATCH * NTOK * CDIM];
__device__ __align__(16) __nv_bfloat16 g_Ol[(size_t)BATCH * NTOK * CDIM];

// ---------------- helpers ----------------------------------------------------
__device__ __forceinline__ uint32_t smem_u32(const void* p) {
    uint32_t a;
    asm("{ .reg .u64 t; cvta.to.shared.u64 t, %1; cvt.u32.u64 %0, t; }"
        : "=r"(a) : "l"(p));
    return a;
}
__device__ __forceinline__ void ldsm4(uint32_t* r, uint32_t addr) {
    asm volatile("ldmatrix.sync.aligned.m8n8.x4.shared.b16 {%0,%1,%2,%3}, [%4];"
                 : "=r"(r[0]), "=r"(r[1]), "=r"(r[2]), "=r"(r[3]) : "r"(addr));
}
__device__ __forceinline__ void mma16816(float* d, const uint32_t* a,
                                         const uint32_t* b) {
    asm volatile(
        "mma.sync.aligned.m16n8k16.row.col.f32.bf16.bf16.f32 "
        "{%0,%1,%2,%3}, {%4,%5,%6,%7}, {%8,%9}, {%0,%1,%2,%3};"
        : "+f"(d[0]), "+f"(d[1]), "+f"(d[2]), "+f"(d[3])
        : "r"(a[0]), "r"(a[1]), "r"(a[2]), "r"(a[3]), "r"(b[0]), "r"(b[1]));
}
__device__ __forceinline__ uint32_t bits2(__nv_bfloat162 v) {
    return *reinterpret_cast<uint32_t*>(&v);
}
__device__ __forceinline__ void split4(float4 v, uint2& hi, uint2& lo) {
    __nv_bfloat162 h01 = __floats2bfloat162_rn(v.x, v.y);
    __nv_bfloat162 h23 = __floats2bfloat162_rn(v.z, v.w);
    __nv_bfloat162 l01 = __floats2bfloat162_rn(v.x - __low2float(h01),
                                               v.y - __high2float(h01));
    __nv_bfloat162 l23 = __floats2bfloat162_rn(v.z - __low2float(h23),
                                               v.w - __high2float(h23));
    hi = make_uint2(bits2(h01), bits2(h23));
    lo = make_uint2(bits2(l01), bits2(l23));
}
__device__ __forceinline__ void split2(float a, float b, uint32_t& hi, uint32_t& lo) {
    __nv_bfloat162 h = __floats2bfloat162_rn(a, b);
    __nv_bfloat162 l = __floats2bfloat162_rn(a - __low2float(h), b - __high2float(h));
    hi = bits2(h);
    lo = bits2(l);
}
__device__ __forceinline__ void cpasync16(uint32_t s, const void* g) {
    asm volatile("cp.async.cg.shared.global [%0], [%1], 16;" :: "r"(s), "l"(g));
}
#define CP_COMMIT() asm volatile("cp.async.commit_group;")
#define CP_WAIT1()  asm volatile("cp.async.wait_group 1;")

// ---------------- operand split kernel --------------------------------------
#define NX4 (BATCH * NTOK * CDIM / 4)   /* 786432  */
#define NW4 (3 * CDIM * CDIM / 4)       /* 442368  */
#define NP4 (CDIM * CDIM / 4)           /* 147456  */
#define TOT4 (NX4 + NW4 + NP4)          /* 1376256 */

__global__ void __launch_bounds__(256) split_all(const float* __restrict__ x,
                                                 const float* __restrict__ wq,
                                                 const float* __restrict__ wp) {
    int i = blockIdx.x * 256 + threadIdx.x;
    const float* src;
    __nv_bfloat16 *dh, *dl;
    int j;
    if (i < NX4) { src = x; dh = g_xh; dl = g_xl; j = i; }
    else if (i < NX4 + NW4) { src = wq; dh = g_wqh; dl = g_wql; j = i - NX4; }
    else if (i < TOT4) { src = wp; dh = g_wph; dl = g_wpl; j = i - NX4 - NW4; }
    else return;
    float4 v = reinterpret_cast<const float4*>(src)[j];
    uint2 hi, lo;
    split4(v, hi, lo);
    reinterpret_cast<uint2*>(dh)[j] = hi;
    reinterpret_cast<uint2*>(dl)[j] = lo;
}

// ---------------- bf16x3 mma.sync GEMM (cp.async 3-stage) --------------------
// C[M,Nc] = A[M,768] @ B[Nc,768]^T from pre-split bf16 hi/lo operands.
// Operand pointers selected in DEVICE code from MODE (never passed from host).
// MODE 0: A=x split, B=w_qkv split; scatter into g_Q*/g_K*/g_V* per-head.
// MODE 1: A=O split, B=w_proj split; C = d_out + bias (fp32).
#define BK 32
#define SSTR 40
#define ATILE_B (128 * SSTR * 2)     /* 10240 */
#define BUF_B   (4 * ATILE_B)        /* 40960 */
#define GSMEM_BYTES (3 * BUF_B)      /* 122880 */
#define NCHUNK (CDIM / BK)           /* 24 */

template <int MODE>
__global__ void __launch_bounds__(256, 1) tcgemm(const float* __restrict__ bias,
                                                 float* __restrict__ Cout) {
    extern __shared__ __align__(128) char smem[];
    const int tid = threadIdx.x;
    const int wid = tid >> 5, lane = tid & 31;
    const int m0w = (wid >> 2) * 64;
    const int n0w = (wid & 3) * 32;
    const int rowBase = blockIdx.y * 128;
    const int colBase = blockIdx.x * 128;
    const uint32_t sbase = smem_u32(smem);

    // device-side operand selection (host must never take &__device__ symbols)
    const __nv_bfloat16* Ah = (MODE == 0) ? g_xh : g_Oh;
    const __nv_bfloat16* Al = (MODE == 0) ? g_xl : g_Ol;
    const __nv_bfloat16* Bh = (MODE == 0) ? g_wqh : g_wph;
    const __nv_bfloat16* Bl = (MODE == 0) ? g_wql : g_wpl;

    const int srow = tid >> 2;        // 0..63
    const int sseg = tid & 3;         // 16B segment within 64B row
    auto stage = [&](int c) {
        if (c < NCHUNK) {
            const uint32_t buf = sbase + (uint32_t)(c % 3) * BUF_B;
            const int k0 = c * BK;
#pragma unroll
            for (int i = 0; i < 8; i++) {
                const int arr = i >> 1;             // 0=Ah 1=Al 2=Bh 3=Bl
                const int row = (i & 1) * 64 + srow;
                const __nv_bfloat16* src =
                    (arr == 0) ? Ah : (arr == 1) ? Al : (arr == 2) ? Bh : Bl;
                const int grow = (arr < 2) ? (rowBase + row) : (colBase + row);
                const void* g = src + (size_t)grow * CDIM + k0 + sseg * 8;
                uint32_t s = buf + (uint32_t)arr * ATILE_B +
                             (uint32_t)(row * SSTR + sseg * 8) * 2;
                cpasync16(s, g);
            }
        }
        CP_COMMIT();
    };

    float acc[4][4][4] = {};
    stage(0);
    stage(1);

    for (int c = 0; c < NCHUNK; c++) {
        CP_WAIT1();
        __syncthreads();
        stage(c + 2);

        const uint32_t bufu = sbase + (uint32_t)(c % 3) * BUF_B;
#pragma unroll
        for (int ks = 0; ks < 2; ks++) {
            const int k16 = ks * 16;
            uint32_t aHi[4][4], aLo[4][4], bHi[2][4], bLo[2][4];

            uint32_t aoff =
                bufu + (uint32_t)((m0w + (lane & 15)) * SSTR + k16 + (lane >> 4) * 8) * 2;
#pragma unroll
            for (int mi = 0; mi < 4; mi++) {
                ldsm4(aHi[mi], aoff + mi * (16 * SSTR * 2));
                ldsm4(aLo[mi], aoff + ATILE_B + mi * (16 * SSTR * 2));
            }
            {
                int g = lane >> 3, w8 = lane & 7;
                uint32_t boff = bufu + 2 * ATILE_B +
                                (uint32_t)((n0w + (g >> 1) * 8 + w8) * SSTR + k16 +
                                           (g & 1) * 8) * 2;
#pragma unroll
                for (int np = 0; np < 2; np++) {
                    ldsm4(bHi[np], boff + np * (16 * SSTR * 2));
                    ldsm4(bLo[np], boff + ATILE_B + np * (16 * SSTR * 2));
                }
            }
            // product-major: 16 independent accumulators between reuses
#pragma unroll
            for (int mi = 0; mi < 4; mi++)
#pragma unroll
                for (int ni = 0; ni < 4; ni++)
                    mma16816(acc[mi][ni], aHi[mi], &bHi[ni >> 1][(ni & 1) * 2]);
#pragma unroll
            for (int mi = 0; mi < 4; mi++)
#pragma unroll
                for (int ni = 0; ni < 4; ni++)
                    mma16816(acc[mi][ni], aHi[mi], &bLo[ni >> 1][(ni & 1) * 2]);
#pragma unroll
            for (int mi = 0; mi < 4; mi++)
#pragma unroll
                for (int ni = 0; ni < 4; ni++)
                    mma16816(acc[mi][ni], aLo[mi], &bHi[ni >> 1][(ni & 1) * 2]);
        }
    }

#pragma unroll
    for (int mi = 0; mi < 4; mi++) {
        int m = rowBase + m0w + 16 * mi + (lane >> 2);
#pragma unroll
        for (int ni = 0; ni < 4; ni++) {
            int e = colBase + n0w + 8 * ni + (lane & 3) * 2;
            if (MODE == 0) {
                int tsel = e / CDIM;
                int rr = e - tsel * CDIM;
                int h = rr >> 6, d = rr & 63;
                __nv_bfloat16* dh = (tsel == 0) ? g_Qh : ((tsel == 1) ? g_Kh : g_Vh);
                __nv_bfloat16* dl = (tsel == 0) ? g_Ql : ((tsel == 1) ? g_Kl : g_Vl);
                int bb = m >> 11, n = m & (NTOK - 1);
                size_t base = ((size_t)(bb * HEADS + h)) * NTOK;
                uint32_t h0, l0, h1, l1;
                split2(acc[mi][ni][0], acc[mi][ni][1], h0, l0);
                split2(acc[mi][ni][2], acc[mi][ni][3], h1, l1);
                size_t i0 = (base + n) * DHEAD + d;
                size_t i1 = (base + n + 8) * DHEAD + d;
                *reinterpret_cast<uint32_t*>(&dh[i0]) = h0;
                *reinterpret_cast<uint32_t*>(&dl[i0]) = l0;
                *reinterpret_cast<uint32_t*>(&dh[i1]) = h1;
                *reinterpret_cast<uint32_t*>(&dl[i1]) = l1;
            } else {
                float2 bv = *reinterpret_cast<const float2*>(&bias[e]);
                float2 v0 = make_float2(acc[mi][ni][0] + bv.x, acc[mi][ni][1] + bv.y);
                float2 v1 = make_float2(acc[mi][ni][2] + bv.x, acc[mi][ni][3] + bv.y);
                *reinterpret_cast<float2*>(&Cout[(size_t)m * CDIM + e]) = v0;
                *reinterpret_cast<float2*>(&Cout[(size_t)(m + 8) * CDIM + e]) = v1;
            }
        }
    }
}

// ---------------- Sliding-window attention, bf16x3 mma.sync ------------------
#define KSLOTS 192
#define QSTR 72
#define KSTR 72
#define PSTR 200
#define VSTR 200
#define SSTRIDE 196
#define OFF_QH 0
#define OFF_QL 9216
#define OFF_KH 18432
#define OFF_KL 46080
#define OFF_S  18432
#define OFF_PH 18432
#define OFF_PL 44032
#define OFF_VTH 73728
#define OFF_VTL 99328
#define ATT_SMEM 124928

__global__ void __launch_bounds__(256) attn_mma() {
    extern __shared__ __align__(128) char sm[];
    const uint32_t sb = smem_u32(sm);
    const int tid = threadIdx.x;
    const int wid = tid >> 5, lane = tid & 31;
    const int q0 = blockIdx.x * 64;
    const int bh = blockIdx.y;
    const int kstart = q0 - HALF;

    const size_t hb = (size_t)bh * NTOK * DHEAD;

    // ---- staging: pure copies of pre-split bf16 ----
    for (int idx = tid; idx < 64 * 16; idx += 256) {
        int q = idx >> 4, d4 = (idx & 15) << 2;
        size_t gi = hb + (size_t)(q0 + q) * DHEAD + d4;
        uint2 hi = *reinterpret_cast<const uint2*>(&g_Qh[gi]);
        uint2 lo = *reinterpret_cast<const uint2*>(&g_Ql[gi]);
        uint32_t off = (uint32_t)(q * QSTR + d4) * 2;
        *reinterpret_cast<uint2*>(sm + OFF_QH + off) = hi;
        *reinterpret_cast<uint2*>(sm + OFF_QL + off) = lo;
    }
    for (int idx = tid; idx < KSLOTS * 16; idx += 256) {
        int s = idx >> 4, d4 = (idx & 15) << 2;
        int j = kstart + s;
        uint2 kh = make_uint2(0, 0), kl = kh, vh = kh, vl = kh;
        if (j >= 0 && j < NTOK) {
            size_t gi = hb + (size_t)j * DHEAD + d4;
            kh = *reinterpret_cast<const uint2*>(&g_Kh[gi]);
            kl = *reinterpret_cast<const uint2*>(&g_Kl[gi]);
            vh = *reinterpret_cast<const uint2*>(&g_Vh[gi]);
            vl = *reinterpret_cast<const uint2*>(&g_Vl[gi]);
        }
        uint32_t off = (uint32_t)(s * KSTR + d4) * 2;
        *reinterpret_cast<uint2*>(sm + OFF_KH + off) = kh;
        *reinterpret_cast<uint2*>(sm + OFF_KL + off) = kl;
        unsigned short* vth = (unsigned short*)(sm + OFF_VTH);
        unsigned short* vtl = (unsigned short*)(sm + OFF_VTL);
        unsigned short he[4] = {(unsigned short)(vh.x & 0xffffu), (unsigned short)(vh.x >> 16),
                                (unsigned short)(vh.y & 0xffffu), (unsigned short)(vh.y >> 16)};
        unsigned short le[4] = {(unsigned short)(vl.x & 0xffffu), (unsigned short)(vl.x >> 16),
                                (unsigned short)(vl.y & 0xffffu), (unsigned short)(vl.y >> 16)};
#pragma unroll
        for (int i = 0; i < 4; i++) {
            vth[(d4 + i) * VSTR + s] = he[i];
            vtl[(d4 + i) * VSTR + s] = le[i];
        }
    }
    __syncthreads();

    // ---- QK^T: warp grid 2x4 (m 2x32, n 4x48) ----
    const int wm = (wid >> 2) * 32;
    const int wn = (wid & 3) * 48;
    float sacc[2][6][4] = {};
    {
        const int g = lane >> 3, w8 = lane & 7;
#pragma unroll
        for (int ks = 0; ks < 4; ks++) {
            const int k16 = ks * 16;
            uint32_t qh[2][4], ql[2][4], kh[3][4], kl[3][4];
            uint32_t aoff = sb + OFF_QH +
                (uint32_t)((wm + (lane & 15)) * QSTR + k16 + (lane >> 4) * 8) * 2;
#pragma unroll
            for (int mi = 0; mi < 2; mi++) {
                ldsm4(qh[mi], aoff + mi * (16 * QSTR * 2));
                ldsm4(ql[mi], aoff + (OFF_QL - OFF_QH) + mi * (16 * QSTR * 2));
            }
            uint32_t boff = sb + OFF_KH +
                (uint32_t)((wn + (g >> 1) * 8 + w8) * KSTR + k16 + (g & 1) * 8) * 2;
#pragma unroll
            for (int np = 0; np < 3; np++) {
                ldsm4(kh[np], boff + np * (16 * KSTR * 2));
                ldsm4(kl[np], boff + (OFF_KL - OFF_KH) + np * (16 * KSTR * 2));
            }
#pragma unroll
            for (int mi = 0; mi < 2; mi++)
#pragma unroll
                for (int nt = 0; nt < 6; nt++)
                    mma16816(sacc[mi][nt], qh[mi], &kh[nt >> 1][(nt & 1) * 2]);
#pragma unroll
            for (int mi = 0; mi < 2; mi++)
#pragma unroll
                for (int nt = 0; nt < 6; nt++)
                    mma16816(sacc[mi][nt], qh[mi], &kl[nt >> 1][(nt & 1) * 2]);
#pragma unroll
            for (int mi = 0; mi < 2; mi++)
#pragma unroll
                for (int nt = 0; nt < 6; nt++)
                    mma16816(sacc[mi][nt], ql[mi], &kh[nt >> 1][(nt & 1) * 2]);
        }
    }
    __syncthreads();  // all K reads done; region becomes S

    // ---- scale + mask, write S fp32 ----
    float* S = (float*)(sm + OFF_S);
#pragma unroll
    for (int mi = 0; mi < 2; mi++) {
        int qA = wm + 16 * mi + (lane >> 2);
#pragma unroll
        for (int nt = 0; nt < 6; nt++) {
            int s0 = wn + 8 * nt + (lane & 3) * 2;
#pragma unroll
            for (int half = 0; half < 2; half++) {
                int q = qA + half * 8;
#pragma unroll
                for (int e = 0; e < 2; e++) {
                    int s = s0 + e;
                    int kj = kstart + s;
                    int diff = q + HALF - s;
                    bool ok = (kj >= 0) & (kj < NTOK) & (diff >= -HALF) & (diff <= HALF);
                    S[q * SSTRIDE + s] =
                        ok ? sacc[mi][nt][half * 2 + e] * SCALE : -3.0e38f;
                }
            }
        }
    }
    __syncthreads();

    // ---- softmax: 4 threads/row, 48 slots each, in registers ----
    {
        const int row = tid >> 2, part = tid & 3;
        const float* srow = S + row * SSTRIDE + part * 48;
        float vals[48];
#pragma unroll
        for (int i = 0; i < 12; i++) {
            float4 v = *reinterpret_cast<const float4*>(srow + 4 * i);
            vals[4 * i] = v.x; vals[4 * i + 1] = v.y;
            vals[4 * i + 2] = v.z; vals[4 * i + 3] = v.w;
        }
        float mx = -3.0e38f;
#pragma unroll
        for (int i = 0; i < 48; i++) mx = fmaxf(mx, vals[i]);
        mx = fmaxf(mx, __shfl_xor_sync(0xffffffff, mx, 1));
        mx = fmaxf(mx, __shfl_xor_sync(0xffffffff, mx, 2));
        float sum = 0.f;
#pragma unroll
        for (int i = 0; i < 48; i++) {
            vals[i] = __expf(vals[i] - mx);
            sum += vals[i];
        }
        sum += __shfl_xor_sync(0xffffffff, sum, 1);
        sum += __shfl_xor_sync(0xffffffff, sum, 2);
        float inv = __fdividef(1.f, sum);
        __syncthreads();  // all S reads complete; region becomes P
        uint32_t pbase = (uint32_t)(row * PSTR + part * 48) * 2;
#pragma unroll
        for (int i = 0; i < 24; i++) {
            uint32_t h, l;
            split2(vals[2 * i] * inv, vals[2 * i + 1] * inv, h, l);
            *reinterpret_cast<uint32_t*>(sm + OFF_PH + pbase + 4 * i) = h;
            *reinterpret_cast<uint32_t*>(sm + OFF_PL + pbase + 4 * i) = l;
        }
    }
    __syncthreads();

    // ---- PV: warp grid 2x4 (m 2x32, n(d) 4x16) ----
    const int wn2 = (wid & 3) * 16;
    float facc[2][2][4] = {};
    {
        const int g = lane >> 3, w8 = lane & 7;
#pragma unroll
        for (int ks = 0; ks < 12; ks++) {
            const int k16 = ks * 16;
            uint32_t ph[2][4], pl[2][4], vh[4], vl[4];
            uint32_t aoff = sb + OFF_PH +
                (uint32_t)((wm + (lane & 15)) * PSTR + k16 + (lane >> 4) * 8) * 2;
#pragma unroll
            for (int mi = 0; mi < 2; mi++) {
                ldsm4(ph[mi], aoff + mi * (16 * PSTR * 2));
                ldsm4(pl[mi], aoff + (OFF_PL - OFF_PH) + mi * (16 * PSTR * 2));
            }
            uint32_t boff = sb + OFF_VTH +
                (uint32_t)((wn2 + (g >> 1) * 8 + w8) * VSTR + k16 + (g & 1) * 8) * 2;
            ldsm4(vh, boff);
            ldsm4(vl, boff + (OFF_VTL - OFF_VTH));
#pragma unroll
            for (int mi = 0; mi < 2; mi++)
#pragma unroll
                for (int nt = 0; nt < 2; nt++)
                    mma16816(facc[mi][nt], ph[mi], &vh[nt * 2]);
#pragma unroll
            for (int mi = 0; mi < 2; mi++)
#pragma unroll
                for (int nt = 0; nt < 2; nt++)
                    mma16816(facc[mi][nt], ph[mi], &vl[nt * 2]);
#pragma unroll
            for (int mi = 0; mi < 2; mi++)
#pragma unroll
                for (int nt = 0; nt < 2; nt++)
                    mma16816(facc[mi][nt], pl[mi], &vh[nt * 2]);
        }
    }

    // ---- epilogue -> g_Oh/g_Ol (bf16 hi/lo, [B,N,C]) ----
    const int b = bh / HEADS, h = bh - b * HEADS;
#pragma unroll
    for (int mi = 0; mi < 2; mi++) {
        int n = q0 + wm + 16 * mi + (lane >> 2);
#pragma unroll
        for (int nt = 0; nt < 2; nt++) {
            int d = wn2 + 8 * nt + (lane & 3) * 2;
            size_t e0 = ((size_t)b * NTOK + n) * CDIM + h * DHEAD + d;
            size_t e1 = e0 + (size_t)8 * CDIM;
            uint32_t h0, l0, h1, l1;
            split2(facc[mi][nt][0], facc[mi][nt][1], h0, l0);
            split2(facc[mi][nt][2], facc[mi][nt][3], h1, l1);
            *reinterpret_cast<uint32_t*>(&g_Oh[e0]) = h0;
            *reinterpret_cast<uint32_t*>(&g_Ol[e0]) = l0;
            *reinterpret_cast<uint32_t*>(&g_Oh[e1]) = h1;
            *reinterpret_cast<uint32_t*>(&g_Ol[e1]) = l1;
        }
    }
}

// ---------------- launch ----------------------------------------------------
extern "C" void kernel_launch(void* const* d_in, const int* in_sizes, int n_in,
                              void* d_out, int out_size) {
    (void)in_sizes; (void)n_in; (void)out_size;
    const float* x      = (const float*)d_in[0];
    const float* w_qkv  = (const float*)d_in[1];
    const float* w_proj = (const float*)d_in[2];
    const float* b_proj = (const float*)d_in[3];
    float* out = (float*)d_out;

    cudaFuncSetAttribute(tcgemm<0>, cudaFuncAttributeMaxDynamicSharedMemorySize,
                         GSMEM_BYTES);
    cudaFuncSetAttribute(tcgemm<1>, cudaFuncAttributeMaxDynamicSharedMemorySize,
                         GSMEM_BYTES);
    cudaFuncSetAttribute(attn_mma, cudaFuncAttributeMaxDynamicSharedMemorySize,
                         ATT_SMEM);

    // 0) split x / w_qkv / w_proj into bf16 hi/lo (device globals written in-kernel)
    split_all<<<(TOT4 + 255) / 256, 256>>>(x, w_qkv, w_proj);

    // 1) QKV projection -> Q/K/V per-head split buffers
    tcgemm<0><<<dim3(3 * CDIM / 128, BATCH * NTOK / 128), 256, GSMEM_BYTES>>>(
        nullptr, nullptr);

    // 2) Sliding-window attention -> g_Oh/g_Ol
    attn_mma<<<dim3(NTOK / 64, BATCH * HEADS), 256, ATT_SMEM>>>();

    // 3) Output projection + bias -> d_out
    tcgemm<1><<<dim3(CDIM / 128, BATCH * NTOK / 128), 256, GSMEM_BYTES>>>(
        b_proj, out);
}

// round 14
// speedup vs baseline: 1.2274x; 1.2274x over previous
#include <cuda_runtime.h>
#include <cuda_bf16.h>
#include <stdint.h>
#include <math.h>

#define BATCH 2
#define NTOK  2048
#define CDIM  768
#define HEADS 12
#define DHEAD 64
#define HALF  64
#define SCALE 0.125f  /* 64^-0.5 */

// ---------------- scratch (device globals; no allocations allowed) ----------
__device__ float g_Q[(size_t)BATCH * HEADS * NTOK * DHEAD];
__device__ float g_K[(size_t)BATCH * HEADS * NTOK * DHEAD];
__device__ float g_V[(size_t)BATCH * HEADS * NTOK * DHEAD];
__device__ float g_O[(size_t)BATCH * NTOK * CDIM];

// ---------------- helpers ----------------------------------------------------
__device__ __forceinline__ uint32_t smem_u32(const void* p) {
    uint32_t a;
    asm("{ .reg .u64 t; cvta.to.shared.u64 t, %1; cvt.u32.u64 %0, t; }"
        : "=r"(a) : "l"(p));
    return a;
}
__device__ __forceinline__ void ldsm4(uint32_t* r, uint32_t addr) {
    asm volatile("ldmatrix.sync.aligned.m8n8.x4.shared.b16 {%0,%1,%2,%3}, [%4];"
                 : "=r"(r[0]), "=r"(r[1]), "=r"(r[2]), "=r"(r[3]) : "r"(addr));
}
__device__ __forceinline__ void mma16816(float* d, const uint32_t* a,
                                         const uint32_t* b) {
    asm volatile(
        "mma.sync.aligned.m16n8k16.row.col.f32.bf16.bf16.f32 "
        "{%0,%1,%2,%3}, {%4,%5,%6,%7}, {%8,%9}, {%0,%1,%2,%3};"
        : "+f"(d[0]), "+f"(d[1]), "+f"(d[2]), "+f"(d[3])
        : "r"(a[0]), "r"(a[1]), "r"(a[2]), "r"(a[3]), "r"(b[0]), "r"(b[1]));
}
__device__ __forceinline__ uint32_t bits2(__nv_bfloat162 v) {
    return *reinterpret_cast<uint32_t*>(&v);
}
__device__ __forceinline__ void split4(float4 v, uint2& hi, uint2& lo) {
    __nv_bfloat162 h01 = __floats2bfloat162_rn(v.x, v.y);
    __nv_bfloat162 h23 = __floats2bfloat162_rn(v.z, v.w);
    __nv_bfloat162 l01 = __floats2bfloat162_rn(v.x - __low2float(h01),
                                               v.y - __high2float(h01));
    __nv_bfloat162 l23 = __floats2bfloat162_rn(v.z - __low2float(h23),
                                               v.w - __high2float(h23));
    hi = make_uint2(bits2(h01), bits2(h23));
    lo = make_uint2(bits2(l01), bits2(l23));
}
__device__ __forceinline__ void split2(float a, float b, uint32_t& hi, uint32_t& lo) {
    __nv_bfloat162 h = __floats2bfloat162_rn(a, b);
    __nv_bfloat162 l = __floats2bfloat162_rn(a - __low2float(h), b - __high2float(h));
    hi = bits2(h);
    lo = bits2(l);
}

// ---------------- bf16x3 mma.sync GEMM: C[M,Nc] = A[M,768] @ B[Nc,768]^T -----
// MODE 0: A = x, scatter 2304 cols into g_Q/g_K/g_V per-head layout.
// MODE 1: A = g_O (device-selected), C = d_out + bias.
// CTA tile 128x64, K-chunk 32, 128 threads (4 warps 2x2, warp tile 64x32).
// Small CTA -> 2 CTAs/SM; one CTA's staging overlaps the other's MMAs.
#define BK 32
#define SSTR 40
#define A_HI (128 * SSTR * 2)      /* 10240 */
#define B_HI (64 * SSTR * 2)       /* 5120  */
#define OFF_AL A_HI                /* 10240 */
#define OFF_BH (2 * A_HI)          /* 20480 */
#define OFF_BL (2 * A_HI + B_HI)   /* 25600 */
#define BUF_B  (2 * A_HI + 2 * B_HI) /* 30720 */
#define GSMEM_BYTES (2 * BUF_B)    /* 61440 */
#define NCHUNK (CDIM / BK)         /* 24 */

template <int MODE>
__global__ void __launch_bounds__(128) tcgemm(const float* __restrict__ A,
                                              const float* __restrict__ Bw,
                                              const float* __restrict__ bias,
                                              float* __restrict__ Cout) {
    extern __shared__ __align__(128) char smem[];
    const int tid = threadIdx.x;
    const int wid = tid >> 5, lane = tid & 31;
    const int m0w = (wid >> 1) * 64;   // warp M offset in tile (0 or 64)
    const int n0w = (wid & 1) * 32;    // warp N offset in tile (0 or 32)
    const int rowBase = blockIdx.y * 128;
    const int colBase = blockIdx.x * 64;
    const float* Asrc = (MODE == 1) ? (const float*)g_O : A;
    const uint32_t sbase = smem_u32(smem);

    const int sr = tid >> 3;        // 0..15 staging row base
    const int sc = (tid & 7) * 4;   // staging col (floats)

    float4 aR[8], bR[4];
    auto ldgch = [&](int k0) {
#pragma unroll
        for (int u = 0; u < 8; u++) {
            int r = u * 16 + sr;
            aR[u] = *reinterpret_cast<const float4*>(
                Asrc + (size_t)(rowBase + r) * CDIM + k0 + sc);
        }
#pragma unroll
        for (int u = 0; u < 4; u++) {
            int r = u * 16 + sr;
            bR[u] = *reinterpret_cast<const float4*>(
                Bw + (size_t)(colBase + r) * CDIM + k0 + sc);
        }
    };

    float acc[4][4][4] = {};
    ldgch(0);

    for (int c = 0; c < NCHUNK; c++) {
        char* bufp = smem + (c & 1) * BUF_B;
        const uint32_t bufu = sbase + (uint32_t)(c & 1) * BUF_B;

        // stage + hi/lo split (same pattern as the proven R9 kernel)
#pragma unroll
        for (int u = 0; u < 8; u++) {
            int r = u * 16 + sr;
            uint32_t off = (uint32_t)(r * SSTR + sc) * 2;
            uint2 hi, lo;
            split4(aR[u], hi, lo);
            *reinterpret_cast<uint2*>(bufp + off) = hi;
            *reinterpret_cast<uint2*>(bufp + OFF_AL + off) = lo;
        }
#pragma unroll
        for (int u = 0; u < 4; u++) {
            int r = u * 16 + sr;
            uint32_t off = (uint32_t)(r * SSTR + sc) * 2;
            uint2 hi, lo;
            split4(bR[u], hi, lo);
            *reinterpret_cast<uint2*>(bufp + OFF_BH + off) = hi;
            *reinterpret_cast<uint2*>(bufp + OFF_BL + off) = lo;
        }
        __syncthreads();

        if (c + 1 < NCHUNK) ldgch((c + 1) * BK);  // prefetch next chunk

#pragma unroll
        for (int ks = 0; ks < 2; ks++) {
            const int k16 = ks * 16;
            uint32_t aHi[4][4], aLo[4][4], bHi[2][4], bLo[2][4];

            uint32_t aoff =
                bufu + (uint32_t)((m0w + (lane & 15)) * SSTR + k16 + (lane >> 4) * 8) * 2;
#pragma unroll
            for (int mi = 0; mi < 4; mi++) {
                ldsm4(aHi[mi], aoff + mi * (16 * SSTR * 2));
                ldsm4(aLo[mi], aoff + OFF_AL + mi * (16 * SSTR * 2));
            }
            {
                int g = lane >> 3, w8 = lane & 7;
                uint32_t boff = bufu + OFF_BH +
                                (uint32_t)((n0w + (g >> 1) * 8 + w8) * SSTR + k16 +
                                           (g & 1) * 8) * 2;
#pragma unroll
                for (int np = 0; np < 2; np++) {
                    ldsm4(bHi[np], boff + np * (16 * SSTR * 2));
                    ldsm4(bLo[np], boff + B_HI + np * (16 * SSTR * 2));
                }
            }
            // product-major: 16 independent accumulators between reuses
#pragma unroll
            for (int mi = 0; mi < 4; mi++)
#pragma unroll
                for (int ni = 0; ni < 4; ni++)
                    mma16816(acc[mi][ni], aHi[mi], &bHi[ni >> 1][(ni & 1) * 2]);
#pragma unroll
            for (int mi = 0; mi < 4; mi++)
#pragma unroll
                for (int ni = 0; ni < 4; ni++)
                    mma16816(acc[mi][ni], aHi[mi], &bLo[ni >> 1][(ni & 1) * 2]);
#pragma unroll
            for (int mi = 0; mi < 4; mi++)
#pragma unroll
                for (int ni = 0; ni < 4; ni++)
                    mma16816(acc[mi][ni], aLo[mi], &bHi[ni >> 1][(ni & 1) * 2]);
        }
        __syncthreads();
    }

    // Epilogue straight from registers.
#pragma unroll
    for (int mi = 0; mi < 4; mi++) {
        int m = rowBase + m0w + 16 * mi + (lane >> 2);
#pragma unroll
        for (int ni = 0; ni < 4; ni++) {
            int e = colBase + n0w + 8 * ni + (lane & 3) * 2;
            float2 v0 = make_float2(acc[mi][ni][0], acc[mi][ni][1]);
            float2 v1 = make_float2(acc[mi][ni][2], acc[mi][ni][3]);
            if (MODE == 0) {
                int tsel = e / CDIM;
                int rr = e - tsel * CDIM;
                int h = rr >> 6, d = rr & 63;
                float* dst = (tsel == 0) ? g_Q : ((tsel == 1) ? g_K : g_V);
                int bb = m >> 11, n = m & (NTOK - 1);
                size_t base = ((size_t)(bb * HEADS + h)) * NTOK;
                *reinterpret_cast<float2*>(&dst[(base + n) * DHEAD + d]) = v0;
                *reinterpret_cast<float2*>(&dst[(base + n + 8) * DHEAD + d]) = v1;
            } else {
                float2 bv = *reinterpret_cast<const float2*>(&bias[e]);
                v0.x += bv.x; v0.y += bv.y;
                v1.x += bv.x; v1.y += bv.y;
                *reinterpret_cast<float2*>(&Cout[(size_t)m * CDIM + e]) = v0;
                *reinterpret_cast<float2*>(&Cout[(size_t)(m + 8) * CDIM + e]) = v1;
            }
        }
    }
}

// ---------------- Sliding-window attention, bf16x3 mma.sync ------------------
// (byte-identical to the 252.7us R9 version)
#define KSLOTS 192
#define QSTR 72
#define KSTR 72
#define PSTR 200
#define VSTR 200
#define SSTRIDE 196
#define OFF_QH 0
#define OFF_QL 9216
#define OFF_KH 18432
#define OFF_KL 46080
#define OFF_S  18432
#define OFF_PH 18432
#define OFF_PL 44032
#define OFF_VTH 73728
#define OFF_VTL 99328
#define ATT_SMEM 124928

__global__ void __launch_bounds__(256) attn_mma() {
    extern __shared__ __align__(128) char sm[];
    const uint32_t sb = smem_u32(sm);
    const int tid = threadIdx.x;
    const int wid = tid >> 5, lane = tid & 31;
    const int q0 = blockIdx.x * 64;
    const int bh = blockIdx.y;
    const int kstart = q0 - HALF;

    const float* Qg = g_Q + (size_t)bh * NTOK * DHEAD;
    const float* Kg = g_K + (size_t)bh * NTOK * DHEAD;
    const float* Vg = g_V + (size_t)bh * NTOK * DHEAD;

    for (int idx = tid; idx < 64 * 16; idx += 256) {
        int q = idx >> 4, d4 = (idx & 15) << 2;
        float4 v = *reinterpret_cast<const float4*>(&Qg[(size_t)(q0 + q) * DHEAD + d4]);
        uint2 hi, lo;
        split4(v, hi, lo);
        uint32_t off = (uint32_t)(q * QSTR + d4) * 2;
        *reinterpret_cast<uint2*>(sm + OFF_QH + off) = hi;
        *reinterpret_cast<uint2*>(sm + OFF_QL + off) = lo;
    }
    for (int idx = tid; idx < KSLOTS * 16; idx += 256) {
        int s = idx >> 4, d4 = (idx & 15) << 2;
        int j = kstart + s;
        float4 kv = make_float4(0.f, 0.f, 0.f, 0.f);
        float4 vv = kv;
        if (j >= 0 && j < NTOK) {
            kv = *reinterpret_cast<const float4*>(&Kg[(size_t)j * DHEAD + d4]);
            vv = *reinterpret_cast<const float4*>(&Vg[(size_t)j * DHEAD + d4]);
        }
        uint2 hi, lo;
        split4(kv, hi, lo);
        uint32_t off = (uint32_t)(s * KSTR + d4) * 2;
        *reinterpret_cast<uint2*>(sm + OFF_KH + off) = hi;
        *reinterpret_cast<uint2*>(sm + OFF_KL + off) = lo;
        float vf[4] = {vv.x, vv.y, vv.z, vv.w};
#pragma unroll
        for (int i = 0; i < 4; i++) {
            __nv_bfloat16 h = __float2bfloat16_rn(vf[i]);
            __nv_bfloat16 l = __float2bfloat16_rn(vf[i] - __bfloat162float(h));
            ((__nv_bfloat16*)(sm + OFF_VTH))[(d4 + i) * VSTR + s] = h;
            ((__nv_bfloat16*)(sm + OFF_VTL))[(d4 + i) * VSTR + s] = l;
        }
    }
    __syncthreads();

    const int wm = (wid >> 2) * 32;
    const int wn = (wid & 3) * 48;
    float sacc[2][6][4] = {};
    {
        const int g = lane >> 3, w8 = lane & 7;
#pragma unroll
        for (int ks = 0; ks < 4; ks++) {
            const int k16 = ks * 16;
            uint32_t qh[2][4], ql[2][4], kh[3][4], kl[3][4];
            uint32_t aoff = sb + OFF_QH +
                (uint32_t)((wm + (lane & 15)) * QSTR + k16 + (lane >> 4) * 8) * 2;
#pragma unroll
            for (int mi = 0; mi < 2; mi++) {
                ldsm4(qh[mi], aoff + mi * (16 * QSTR * 2));
                ldsm4(ql[mi], aoff + (OFF_QL - OFF_QH) + mi * (16 * QSTR * 2));
            }
            uint32_t boff = sb + OFF_KH +
                (uint32_t)((wn + (g >> 1) * 8 + w8) * KSTR + k16 + (g & 1) * 8) * 2;
#pragma unroll
            for (int np = 0; np < 3; np++) {
                ldsm4(kh[np], boff + np * (16 * KSTR * 2));
                ldsm4(kl[np], boff + (OFF_KL - OFF_KH) + np * (16 * KSTR * 2));
            }
#pragma unroll
            for (int mi = 0; mi < 2; mi++)
#pragma unroll
                for (int nt = 0; nt < 6; nt++)
                    mma16816(sacc[mi][nt], qh[mi], &kh[nt >> 1][(nt & 1) * 2]);
#pragma unroll
            for (int mi = 0; mi < 2; mi++)
#pragma unroll
                for (int nt = 0; nt < 6; nt++)
                    mma16816(sacc[mi][nt], qh[mi], &kl[nt >> 1][(nt & 1) * 2]);
#pragma unroll
            for (int mi = 0; mi < 2; mi++)
#pragma unroll
                for (int nt = 0; nt < 6; nt++)
                    mma16816(sacc[mi][nt], ql[mi], &kh[nt >> 1][(nt & 1) * 2]);
        }
    }
    __syncthreads();

    float* S = (float*)(sm + OFF_S);
#pragma unroll
    for (int mi = 0; mi < 2; mi++) {
        int qA = wm + 16 * mi + (lane >> 2);
#pragma unroll
        for (int nt = 0; nt < 6; nt++) {
            int s0 = wn + 8 * nt + (lane & 3) * 2;
#pragma unroll
            for (int half = 0; half < 2; half++) {
                int q = qA + half * 8;
#pragma unroll
                for (int e = 0; e < 2; e++) {
                    int s = s0 + e;
                    int kj = kstart + s;
                    int diff = q + HALF - s;
                    bool ok = (kj >= 0) & (kj < NTOK) & (diff >= -HALF) & (diff <= HALF);
                    S[q * SSTRIDE + s] =
                        ok ? sacc[mi][nt][half * 2 + e] * SCALE : -3.0e38f;
                }
            }
        }
    }
    __syncthreads();

    {
        const int row = tid >> 2, part = tid & 3;
        const float* srow = S + row * SSTRIDE + part * 48;
        float vals[48];
#pragma unroll
        for (int i = 0; i < 12; i++) {
            float4 v = *reinterpret_cast<const float4*>(srow + 4 * i);
            vals[4 * i] = v.x; vals[4 * i + 1] = v.y;
            vals[4 * i + 2] = v.z; vals[4 * i + 3] = v.w;
        }
        float mx = -3.0e38f;
#pragma unroll
        for (int i = 0; i < 48; i++) mx = fmaxf(mx, vals[i]);
        mx = fmaxf(mx, __shfl_xor_sync(0xffffffff, mx, 1));
        mx = fmaxf(mx, __shfl_xor_sync(0xffffffff, mx, 2));
        float sum = 0.f;
#pragma unroll
        for (int i = 0; i < 48; i++) {
            vals[i] = __expf(vals[i] - mx);
            sum += vals[i];
        }
        sum += __shfl_xor_sync(0xffffffff, sum, 1);
        sum += __shfl_xor_sync(0xffffffff, sum, 2);
        float inv = __fdividef(1.f, sum);
        __syncthreads();
        uint32_t pbase = (uint32_t)(row * PSTR + part * 48) * 2;
#pragma unroll
        for (int i = 0; i < 24; i++) {
            uint32_t h, l;
            split2(vals[2 * i] * inv, vals[2 * i + 1] * inv, h, l);
            *reinterpret_cast<uint32_t*>(sm + OFF_PH + pbase + 4 * i) = h;
            *reinterpret_cast<uint32_t*>(sm + OFF_PL + pbase + 4 * i) = l;
        }
    }
    __syncthreads();

    const int wn2 = (wid & 3) * 16;
    float facc[2][2][4] = {};
    {
        const int g = lane >> 3, w8 = lane & 7;
#pragma unroll
        for (int ks = 0; ks < 12; ks++) {
            const int k16 = ks * 16;
            uint32_t ph[2][4], pl[2][4], vh[4], vl[4];
            uint32_t aoff = sb + OFF_PH +
                (uint32_t)((wm + (lane & 15)) * PSTR + k16 + (lane >> 4) * 8) * 2;
#pragma unroll
            for (int mi = 0; mi < 2; mi++) {
                ldsm4(ph[mi], aoff + mi * (16 * PSTR * 2));
                ldsm4(pl[mi], aoff + (OFF_PL - OFF_PH) + mi * (16 * PSTR * 2));
            }
            uint32_t boff = sb + OFF_VTH +
                (uint32_t)((wn2 + (g >> 1) * 8 + w8) * VSTR + k16 + (g & 1) * 8) * 2;
            ldsm4(vh, boff);
            ldsm4(vl, boff + (OFF_VTL - OFF_VTH));
#pragma unroll
            for (int mi = 0; mi < 2; mi++)
#pragma unroll
                for (int nt = 0; nt < 2; nt++)
                    mma16816(facc[mi][nt], ph[mi], &vh[nt * 2]);
#pragma unroll
            for (int mi = 0; mi < 2; mi++)
#pragma unroll
                for (int nt = 0; nt < 2; nt++)
                    mma16816(facc[mi][nt], ph[mi], &vl[nt * 2]);
#pragma unroll
            for (int mi = 0; mi < 2; mi++)
#pragma unroll
                for (int nt = 0; nt < 2; nt++)
                    mma16816(facc[mi][nt], pl[mi], &vh[nt * 2]);
        }
    }

    const int b = bh / HEADS, h = bh - b * HEADS;
#pragma unroll
    for (int mi = 0; mi < 2; mi++) {
        int n = q0 + wm + 16 * mi + (lane >> 2);
#pragma unroll
        for (int nt = 0; nt < 2; nt++) {
            int d = wn2 + 8 * nt + (lane & 3) * 2;
            float* p0 = &g_O[((size_t)b * NTOK + n) * CDIM + h * DHEAD + d];
            float* p1 = &g_O[((size_t)b * NTOK + n + 8) * CDIM + h * DHEAD + d];
            *reinterpret_cast<float2*>(p0) = make_float2(facc[mi][nt][0], facc[mi][nt][1]);
            *reinterpret_cast<float2*>(p1) = make_float2(facc[mi][nt][2], facc[mi][nt][3]);
        }
    }
}

// ---------------- launch ----------------------------------------------------
extern "C" void kernel_launch(void* const* d_in, const int* in_sizes, int n_in,
                              void* d_out, int out_size) {
    (void)in_sizes; (void)n_in; (void)out_size;
    const float* x      = (const float*)d_in[0];
    const float* w_qkv  = (const float*)d_in[1];
    const float* w_proj = (const float*)d_in[2];
    const float* b_proj = (const float*)d_in[3];
    float* out = (float*)d_out;

    cudaFuncSetAttribute(tcgemm<0>, cudaFuncAttributeMaxDynamicSharedMemorySize,
                         GSMEM_BYTES);
    cudaFuncSetAttribute(tcgemm<1>, cudaFuncAttributeMaxDynamicSharedMemorySize,
                         GSMEM_BYTES);
    cudaFuncSetAttribute(attn_mma, cudaFuncAttributeMaxDynamicSharedMemorySize,
                         ATT_SMEM);

    // 1) QKV projection (bf16x3 mma.sync, 128x64 tiles) -> Q/K/V buffers
    tcgemm<0><<<dim3(3 * CDIM / 64, BATCH * NTOK / 128), 128, GSMEM_BYTES>>>(
        x, w_qkv, nullptr, nullptr);

    // 2) Sliding-window attention (bf16x3 mma.sync) -> g_O ([B,N,C] layout)
    attn_mma<<<dim3(NTOK / 64, BATCH * HEADS), 256, ATT_SMEM>>>();

    // 3) Output projection + bias (bf16x3 mma.sync, 128x64 tiles) -> d_out
    tcgemm<1><<<dim3(CDIM / 64, BATCH * NTOK / 128), 128, GSMEM_BYTES>>>(
        nullptr, w_proj, b_proj, out);
}

// round 15
// speedup vs baseline: 1.2585x; 1.0253x over previous
#include <cuda_runtime.h>
#include <cuda_bf16.h>
#include <stdint.h>
#include <math.h>

#define BATCH 2
#define NTOK  2048
#define CDIM  768
#define HEADS 12
#define DHEAD 64
#define HALF  64
#define SCALE 0.125f  /* 64^-0.5 */

// ---------------- scratch (device globals; no allocations allowed) ----------
__device__ float g_Q[(size_t)BATCH * HEADS * NTOK * DHEAD];
__device__ float g_K[(size_t)BATCH * HEADS * NTOK * DHEAD];
__device__ float g_V[(size_t)BATCH * HEADS * NTOK * DHEAD];
__device__ float g_O[(size_t)BATCH * NTOK * CDIM];

// ---------------- helpers ----------------------------------------------------
__device__ __forceinline__ uint32_t smem_u32(const void* p) {
    uint32_t a;
    asm("{ .reg .u64 t; cvta.to.shared.u64 t, %1; cvt.u32.u64 %0, t; }"
        : "=r"(a) : "l"(p));
    return a;
}
__device__ __forceinline__ void ldsm4(uint32_t* r, uint32_t addr) {
    asm volatile("ldmatrix.sync.aligned.m8n8.x4.shared.b16 {%0,%1,%2,%3}, [%4];"
                 : "=r"(r[0]), "=r"(r[1]), "=r"(r[2]), "=r"(r[3]) : "r"(addr));
}
__device__ __forceinline__ void mma16816(float* d, const uint32_t* a,
                                         const uint32_t* b) {
    asm volatile(
        "mma.sync.aligned.m16n8k16.row.col.f32.bf16.bf16.f32 "
        "{%0,%1,%2,%3}, {%4,%5,%6,%7}, {%8,%9}, {%0,%1,%2,%3};"
        : "+f"(d[0]), "+f"(d[1]), "+f"(d[2]), "+f"(d[3])
        : "r"(a[0]), "r"(a[1]), "r"(a[2]), "r"(a[3]), "r"(b[0]), "r"(b[1]));
}
__device__ __forceinline__ uint32_t bits2(__nv_bfloat162 v) {
    return *reinterpret_cast<uint32_t*>(&v);
}
__device__ __forceinline__ void split4(float4 v, uint2& hi, uint2& lo) {
    __nv_bfloat162 h01 = __floats2bfloat162_rn(v.x, v.y);
    __nv_bfloat162 h23 = __floats2bfloat162_rn(v.z, v.w);
    __nv_bfloat162 l01 = __floats2bfloat162_rn(v.x - __low2float(h01),
                                               v.y - __high2float(h01));
    __nv_bfloat162 l23 = __floats2bfloat162_rn(v.z - __low2float(h23),
                                               v.w - __high2float(h23));
    hi = make_uint2(bits2(h01), bits2(h23));
    lo = make_uint2(bits2(l01), bits2(l23));
}
__device__ __forceinline__ void split2(float a, float b, uint32_t& hi, uint32_t& lo) {
    __nv_bfloat162 h = __floats2bfloat162_rn(a, b);
    __nv_bfloat162 l = __floats2bfloat162_rn(a - __low2float(h), b - __high2float(h));
    hi = bits2(h);
    lo = bits2(l);
}

// ---------------- bf16x3 mma.sync GEMM: C[M,Nc] = A[M,768] @ B[Nc,768]^T -----
// MODE 0: A = x, scatter 2304 cols into g_Q/g_K/g_V per-head layout.
// MODE 1: A = g_O (device-selected), C = d_out + bias.
// CTA tile 128x128, K-chunk 32, 128 threads (4 warps 2x2, warp tile 64x64).
// 64x64 warp tile cuts LDSM bytes/HMMA by 33% and STS+LDG per HMMA by 2x
// (the l1tex pipe, not tensor, was binding at warp tile 64x32).
#define BK 32
#define SSTR 40
#define T_HI (128 * SSTR * 2)      /* 10240 : one hi or lo plane of a 128x32 tile */
#define OFF_AL T_HI                /* 10240 */
#define OFF_BH (2 * T_HI)          /* 20480 */
#define OFF_BL (3 * T_HI)          /* 30720 */
#define BUF_B  (4 * T_HI)          /* 40960 */
#define GSMEM_BYTES (2 * BUF_B)    /* 81920 -> 2 CTAs/SM by smem */
#define NCHUNK (CDIM / BK)         /* 24 */

template <int MODE>
__global__ void __launch_bounds__(128) tcgemm(const float* __restrict__ A,
                                              const float* __restrict__ Bw,
                                              const float* __restrict__ bias,
                                              float* __restrict__ Cout) {
    extern __shared__ __align__(128) char smem[];
    const int tid = threadIdx.x;
    const int wid = tid >> 5, lane = tid & 31;
    const int m0w = (wid >> 1) * 64;   // warp M offset (0 or 64)
    const int n0w = (wid & 1) * 64;    // warp N offset (0 or 64)
    const int rowBase = blockIdx.y * 128;
    const int colBase = blockIdx.x * 128;
    const float* Asrc = (MODE == 1) ? (const float*)g_O : A;
    const uint32_t sbase = smem_u32(smem);

    const int sr = tid >> 3;        // 0..15 staging row base
    const int sc = (tid & 7) * 4;   // staging col (floats)

    // A prefetched through registers (proven pattern); B staged directly
    // (weights are L2-hot: 18/6 B-panels shared by all CTAs).
    float4 aR[8];
    auto ldgA = [&](int k0) {
#pragma unroll
        for (int u = 0; u < 8; u++) {
            int r = u * 16 + sr;
            aR[u] = *reinterpret_cast<const float4*>(
                Asrc + (size_t)(rowBase + r) * CDIM + k0 + sc);
        }
    };

    float acc[4][8][4] = {};
    ldgA(0);

    for (int c = 0; c < NCHUNK; c++) {
        char* bufp = smem + (c & 1) * BUF_B;
        const uint32_t bufu = sbase + (uint32_t)(c & 1) * BUF_B;
        const int k0 = c * BK;

        // stage A from registers
#pragma unroll
        for (int u = 0; u < 8; u++) {
            int r = u * 16 + sr;
            uint32_t off = (uint32_t)(r * SSTR + sc) * 2;
            uint2 hi, lo;
            split4(aR[u], hi, lo);
            *reinterpret_cast<uint2*>(bufp + off) = hi;
            *reinterpret_cast<uint2*>(bufp + OFF_AL + off) = lo;
        }
        // stage B directly (LDG -> split -> STS)
#pragma unroll
        for (int u = 0; u < 8; u++) {
            int r = u * 16 + sr;
            float4 v = *reinterpret_cast<const float4*>(
                Bw + (size_t)(colBase + r) * CDIM + k0 + sc);
            uint32_t off = (uint32_t)(r * SSTR + sc) * 2;
            uint2 hi, lo;
            split4(v, hi, lo);
            *reinterpret_cast<uint2*>(bufp + OFF_BH + off) = hi;
            *reinterpret_cast<uint2*>(bufp + OFF_BL + off) = lo;
        }
        __syncthreads();

        if (c + 1 < NCHUNK) ldgA((c + 1) * BK);  // prefetch next A chunk

#pragma unroll
        for (int ks = 0; ks < 2; ks++) {
            const int k16 = ks * 16;
            uint32_t aHi[4][4], aLo[4][4], bHi[4][4], bLo[4][4];

            uint32_t aoff =
                bufu + (uint32_t)((m0w + (lane & 15)) * SSTR + k16 + (lane >> 4) * 8) * 2;
#pragma unroll
            for (int mi = 0; mi < 4; mi++) {
                ldsm4(aHi[mi], aoff + mi * (16 * SSTR * 2));
                ldsm4(aLo[mi], aoff + OFF_AL + mi * (16 * SSTR * 2));
            }
            {
                int g = lane >> 3, w8 = lane & 7;
                uint32_t boff = bufu + OFF_BH +
                                (uint32_t)((n0w + (g >> 1) * 8 + w8) * SSTR + k16 +
                                           (g & 1) * 8) * 2;
#pragma unroll
                for (int np = 0; np < 4; np++) {
                    ldsm4(bHi[np], boff + np * (16 * SSTR * 2));
                    ldsm4(bLo[np], boff + T_HI + np * (16 * SSTR * 2));
                }
            }
            // product-major: 32 independent accumulators between reuses
#pragma unroll
            for (int mi = 0; mi < 4; mi++)
#pragma unroll
                for (int ni = 0; ni < 8; ni++)
                    mma16816(acc[mi][ni], aHi[mi], &bHi[ni >> 1][(ni & 1) * 2]);
#pragma unroll
            for (int mi = 0; mi < 4; mi++)
#pragma unroll
                for (int ni = 0; ni < 8; ni++)
                    mma16816(acc[mi][ni], aHi[mi], &bLo[ni >> 1][(ni & 1) * 2]);
#pragma unroll
            for (int mi = 0; mi < 4; mi++)
#pragma unroll
                for (int ni = 0; ni < 8; ni++)
                    mma16816(acc[mi][ni], aLo[mi], &bHi[ni >> 1][(ni & 1) * 2]);
        }
        __syncthreads();
    }

    // Epilogue straight from registers.
#pragma unroll
    for (int mi = 0; mi < 4; mi++) {
        int m = rowBase + m0w + 16 * mi + (lane >> 2);
#pragma unroll
        for (int ni = 0; ni < 8; ni++) {
            int e = colBase + n0w + 8 * ni + (lane & 3) * 2;
            float2 v0 = make_float2(acc[mi][ni][0], acc[mi][ni][1]);
            float2 v1 = make_float2(acc[mi][ni][2], acc[mi][ni][3]);
            if (MODE == 0) {
                int tsel = e / CDIM;
                int rr = e - tsel * CDIM;
                int h = rr >> 6, d = rr & 63;
                float* dst = (tsel == 0) ? g_Q : ((tsel == 1) ? g_K : g_V);
                int bb = m >> 11, n = m & (NTOK - 1);
                size_t base = ((size_t)(bb * HEADS + h)) * NTOK;
                *reinterpret_cast<float2*>(&dst[(base + n) * DHEAD + d]) = v0;
                *reinterpret_cast<float2*>(&dst[(base + n + 8) * DHEAD + d]) = v1;
            } else {
                float2 bv = *reinterpret_cast<const float2*>(&bias[e]);
                v0.x += bv.x; v0.y += bv.y;
                v1.x += bv.x; v1.y += bv.y;
                *reinterpret_cast<float2*>(&Cout[(size_t)m * CDIM + e]) = v0;
                *reinterpret_cast<float2*>(&Cout[(size_t)(m + 8) * CDIM + e]) = v1;
            }
        }
    }
}

// ---------------- Sliding-window attention, bf16x3 mma.sync ------------------
// (byte-identical to the passing R14 version)
#define KSLOTS 192
#define QSTR 72
#define KSTR 72
#define PSTR 200
#define VSTR 200
#define SSTRIDE 196
#define OFF_QH 0
#define OFF_QL 9216
#define OFF_KH 18432
#define OFF_KL 46080
#define OFF_S  18432
#define OFF_PH 18432
#define OFF_PL 44032
#define OFF_VTH 73728
#define OFF_VTL 99328
#define ATT_SMEM 124928

__global__ void __launch_bounds__(256) attn_mma() {
    extern __shared__ __align__(128) char sm[];
    const uint32_t sb = smem_u32(sm);
    const int tid = threadIdx.x;
    const int wid = tid >> 5, lane = tid & 31;
    const int q0 = blockIdx.x * 64;
    const int bh = blockIdx.y;
    const int kstart = q0 - HALF;

    const float* Qg = g_Q + (size_t)bh * NTOK * DHEAD;
    const float* Kg = g_K + (size_t)bh * NTOK * DHEAD;
    const float* Vg = g_V + (size_t)bh * NTOK * DHEAD;

    for (int idx = tid; idx < 64 * 16; idx += 256) {
        int q = idx >> 4, d4 = (idx & 15) << 2;
        float4 v = *reinterpret_cast<const float4*>(&Qg[(size_t)(q0 + q) * DHEAD + d4]);
        uint2 hi, lo;
        split4(v, hi, lo);
        uint32_t off = (uint32_t)(q * QSTR + d4) * 2;
        *reinterpret_cast<uint2*>(sm + OFF_QH + off) = hi;
        *reinterpret_cast<uint2*>(sm + OFF_QL + off) = lo;
    }
    for (int idx = tid; idx < KSLOTS * 16; idx += 256) {
        int s = idx >> 4, d4 = (idx & 15) << 2;
        int j = kstart + s;
        float4 kv = make_float4(0.f, 0.f, 0.f, 0.f);
        float4 vv = kv;
        if (j >= 0 && j < NTOK) {
            kv = *reinterpret_cast<const float4*>(&Kg[(size_t)j * DHEAD + d4]);
            vv = *reinterpret_cast<const float4*>(&Vg[(size_t)j * DHEAD + d4]);
        }
        uint2 hi, lo;
        split4(kv, hi, lo);
        uint32_t off = (uint32_t)(s * KSTR + d4) * 2;
        *reinterpret_cast<uint2*>(sm + OFF_KH + off) = hi;
        *reinterpret_cast<uint2*>(sm + OFF_KL + off) = lo;
        float vf[4] = {vv.x, vv.y, vv.z, vv.w};
#pragma unroll
        for (int i = 0; i < 4; i++) {
            __nv_bfloat16 h = __float2bfloat16_rn(vf[i]);
            __nv_bfloat16 l = __float2bfloat16_rn(vf[i] - __bfloat162float(h));
            ((__nv_bfloat16*)(sm + OFF_VTH))[(d4 + i) * VSTR + s] = h;
            ((__nv_bfloat16*)(sm + OFF_VTL))[(d4 + i) * VSTR + s] = l;
        }
    }
    __syncthreads();

    const int wm = (wid >> 2) * 32;
    const int wn = (wid & 3) * 48;
    float sacc[2][6][4] = {};
    {
        const int g = lane >> 3, w8 = lane & 7;
#pragma unroll
        for (int ks = 0; ks < 4; ks++) {
            const int k16 = ks * 16;
            uint32_t qh[2][4], ql[2][4], kh[3][4], kl[3][4];
            uint32_t aoff = sb + OFF_QH +
                (uint32_t)((wm + (lane & 15)) * QSTR + k16 + (lane >> 4) * 8) * 2;
#pragma unroll
            for (int mi = 0; mi < 2; mi++) {
                ldsm4(qh[mi], aoff + mi * (16 * QSTR * 2));
                ldsm4(ql[mi], aoff + (OFF_QL - OFF_QH) + mi * (16 * QSTR * 2));
            }
            uint32_t boff = sb + OFF_KH +
                (uint32_t)((wn + (g >> 1) * 8 + w8) * KSTR + k16 + (g & 1) * 8) * 2;
#pragma unroll
            for (int np = 0; np < 3; np++) {
                ldsm4(kh[np], boff + np * (16 * KSTR * 2));
                ldsm4(kl[np], boff + (OFF_KL - OFF_KH) + np * (16 * KSTR * 2));
            }
#pragma unroll
            for (int mi = 0; mi < 2; mi++)
#pragma unroll
                for (int nt = 0; nt < 6; nt++)
                    mma16816(sacc[mi][nt], qh[mi], &kh[nt >> 1][(nt & 1) * 2]);
#pragma unroll
            for (int mi = 0; mi < 2; mi++)
#pragma unroll
                for (int nt = 0; nt < 6; nt++)
                    mma16816(sacc[mi][nt], qh[mi], &kl[nt >> 1][(nt & 1) * 2]);
#pragma unroll
            for (int mi = 0; mi < 2; mi++)
#pragma unroll
                for (int nt = 0; nt < 6; nt++)
                    mma16816(sacc[mi][nt], ql[mi], &kh[nt >> 1][(nt & 1) * 2]);
        }
    }
    __syncthreads();

    float* S = (float*)(sm + OFF_S);
#pragma unroll
    for (int mi = 0; mi < 2; mi++) {
        int qA = wm + 16 * mi + (lane >> 2);
#pragma unroll
        for (int nt = 0; nt < 6; nt++) {
            int s0 = wn + 8 * nt + (lane & 3) * 2;
#pragma unroll
            for (int half = 0; half < 2; half++) {
                int q = qA + half * 8;
#pragma unroll
                for (int e = 0; e < 2; e++) {
                    int s = s0 + e;
                    int kj = kstart + s;
                    int diff = q + HALF - s;
                    bool ok = (kj >= 0) & (kj < NTOK) & (diff >= -HALF) & (diff <= HALF);
                    S[q * SSTRIDE + s] =
                        ok ? sacc[mi][nt][half * 2 + e] * SCALE : -3.0e38f;
                }
            }
        }
    }
    __syncthreads();

    {
        const int row = tid >> 2, part = tid & 3;
        const float* srow = S + row * SSTRIDE + part * 48;
        float vals[48];
#pragma unroll
        for (int i = 0; i < 12; i++) {
            float4 v = *reinterpret_cast<const float4*>(srow + 4 * i);
            vals[4 * i] = v.x; vals[4 * i + 1] = v.y;
            vals[4 * i + 2] = v.z; vals[4 * i + 3] = v.w;
        }
        float mx = -3.0e38f;
#pragma unroll
        for (int i = 0; i < 48; i++) mx = fmaxf(mx, vals[i]);
        mx = fmaxf(mx, __shfl_xor_sync(0xffffffff, mx, 1));
        mx = fmaxf(mx, __shfl_xor_sync(0xffffffff, mx, 2));
        float sum = 0.f;
#pragma unroll
        for (int i = 0; i < 48; i++) {
            vals[i] = __expf(vals[i] - mx);
            sum += vals[i];
        }
        sum += __shfl_xor_sync(0xffffffff, sum, 1);
        sum += __shfl_xor_sync(0xffffffff, sum, 2);
        float inv = __fdividef(1.f, sum);
        __syncthreads();
        uint32_t pbase = (uint32_t)(row * PSTR + part * 48) * 2;
#pragma unroll
        for (int i = 0; i < 24; i++) {
            uint32_t h, l;
            split2(vals[2 * i] * inv, vals[2 * i + 1] * inv, h, l);
            *reinterpret_cast<uint32_t*>(sm + OFF_PH + pbase + 4 * i) = h;
            *reinterpret_cast<uint32_t*>(sm + OFF_PL + pbase + 4 * i) = l;
        }
    }
    __syncthreads();

    const int wn2 = (wid & 3) * 16;
    float facc[2][2][4] = {};
    {
        const int g = lane >> 3, w8 = lane & 7;
#pragma unroll
        for (int ks = 0; ks < 12; ks++) {
            const int k16 = ks * 16;
            uint32_t ph[2][4], pl[2][4], vh[4], vl[4];
            uint32_t aoff = sb + OFF_PH +
                (uint32_t)((wm + (lane & 15)) * PSTR + k16 + (lane >> 4) * 8) * 2;
#pragma unroll
            for (int mi = 0; mi < 2; mi++) {
                ldsm4(ph[mi], aoff + mi * (16 * PSTR * 2));
                ldsm4(pl[mi], aoff + (OFF_PL - OFF_PH) + mi * (16 * PSTR * 2));
            }
            uint32_t boff = sb + OFF_VTH +
                (uint32_t)((wn2 + (g >> 1) * 8 + w8) * VSTR + k16 + (g & 1) * 8) * 2;
            ldsm4(vh, boff);
            ldsm4(vl, boff + (OFF_VTL - OFF_VTH));
#pragma unroll
            for (int mi = 0; mi < 2; mi++)
#pragma unroll
                for (int nt = 0; nt < 2; nt++)
                    mma16816(facc[mi][nt], ph[mi], &vh[nt * 2]);
#pragma unroll
            for (int mi = 0; mi < 2; mi++)
#pragma unroll
                for (int nt = 0; nt < 2; nt++)
                    mma16816(facc[mi][nt], ph[mi], &vl[nt * 2]);
#pragma unroll
            for (int mi = 0; mi < 2; mi++)
#pragma unroll
                for (int nt = 0; nt < 2; nt++)
                    mma16816(facc[mi][nt], pl[mi], &vh[nt * 2]);
        }
    }

    const int b = bh / HEADS, h = bh - b * HEADS;
#pragma unroll
    for (int mi = 0; mi < 2; mi++) {
        int n = q0 + wm + 16 * mi + (lane >> 2);
#pragma unroll
        for (int nt = 0; nt < 2; nt++) {
            int d = wn2 + 8 * nt + (lane & 3) * 2;
            float* p0 = &g_O[((size_t)b * NTOK + n) * CDIM + h * DHEAD + d];
            float* p1 = &g_O[((size_t)b * NTOK + n + 8) * CDIM + h * DHEAD + d];
            *reinterpret_cast<float2*>(p0) = make_float2(facc[mi][nt][0], facc[mi][nt][1]);
            *reinterpret_cast<float2*>(p1) = make_float2(facc[mi][nt][2], facc[mi][nt][3]);
        }
    }
}

// ---------------- launch ----------------------------------------------------
extern "C" void kernel_launch(void* const* d_in, const int* in_sizes, int n_in,
                              void* d_out, int out_size) {
    (void)in_sizes; (void)n_in; (void)out_size;
    const float* x      = (const float*)d_in[0];
    const float* w_qkv  = (const float*)d_in[1];
    const float* w_proj = (const float*)d_in[2];
    const float* b_proj = (const float*)d_in[3];
    float* out = (float*)d_out;

    cudaFuncSetAttribute(tcgemm<0>, cudaFuncAttributeMaxDynamicSharedMemorySize,
                         GSMEM_BYTES);
    cudaFuncSetAttribute(tcgemm<1>, cudaFuncAttributeMaxDynamicSharedMemorySize,
                         GSMEM_BYTES);
    cudaFuncSetAttribute(attn_mma, cudaFuncAttributeMaxDynamicSharedMemorySize,
                         ATT_SMEM);

    // 1) QKV projection (bf16x3 mma.sync, 128x128 tiles, 64x64 warp tiles)
    tcgemm<0><<<dim3(3 * CDIM / 128, BATCH * NTOK / 128), 128, GSMEM_BYTES>>>(
        x, w_qkv, nullptr, nullptr);

    // 2) Sliding-window attention (bf16x3 mma.sync) -> g_O ([B,N,C] layout)
    attn_mma<<<dim3(NTOK / 64, BATCH * HEADS), 256, ATT_SMEM>>>();

    // 3) Output projection + bias -> d_out
    tcgemm<1><<<dim3(CDIM / 128, BATCH * NTOK / 128), 128, GSMEM_BYTES>>>(
        nullptr, w_proj, b_proj, out);
}

// round 16
// speedup vs baseline: 1.2953x; 1.0293x over previous
#include <cuda_runtime.h>
#include <cuda_bf16.h>
#include <stdint.h>
#include <math.h>

#define BATCH 2
#define NTOK  2048
#define CDIM  768
#define HEADS 12
#define DHEAD 64
#define HALF  64
#define SCALE 0.125f  /* 64^-0.5 */

// ---------------- scratch (device globals; no allocations allowed) ----------
__device__ float g_Q[(size_t)BATCH * HEADS * NTOK * DHEAD];
__device__ float g_K[(size_t)BATCH * HEADS * NTOK * DHEAD];
__device__ float g_V[(size_t)BATCH * HEADS * NTOK * DHEAD];
__device__ float g_O[(size_t)BATCH * NTOK * CDIM];

// ---------------- helpers ----------------------------------------------------
__device__ __forceinline__ uint32_t smem_u32(const void* p) {
    uint32_t a;
    asm("{ .reg .u64 t; cvta.to.shared.u64 t, %1; cvt.u32.u64 %0, t; }"
        : "=r"(a) : "l"(p));
    return a;
}
__device__ __forceinline__ void ldsm4(uint32_t* r, uint32_t addr) {
    asm volatile("ldmatrix.sync.aligned.m8n8.x4.shared.b16 {%0,%1,%2,%3}, [%4];"
                 : "=r"(r[0]), "=r"(r[1]), "=r"(r[2]), "=r"(r[3]) : "r"(addr));
}
__device__ __forceinline__ void mma16816(float* d, const uint32_t* a,
                                         const uint32_t* b) {
    asm volatile(
        "mma.sync.aligned.m16n8k16.row.col.f32.bf16.bf16.f32 "
        "{%0,%1,%2,%3}, {%4,%5,%6,%7}, {%8,%9}, {%0,%1,%2,%3};"
        : "+f"(d[0]), "+f"(d[1]), "+f"(d[2]), "+f"(d[3])
        : "r"(a[0]), "r"(a[1]), "r"(a[2]), "r"(a[3]), "r"(b[0]), "r"(b[1]));
}
__device__ __forceinline__ uint32_t bits2(__nv_bfloat162 v) {
    return *reinterpret_cast<uint32_t*>(&v);
}
__device__ __forceinline__ void split4(float4 v, uint2& hi, uint2& lo) {
    __nv_bfloat162 h01 = __floats2bfloat162_rn(v.x, v.y);
    __nv_bfloat162 h23 = __floats2bfloat162_rn(v.z, v.w);
    __nv_bfloat162 l01 = __floats2bfloat162_rn(v.x - __low2float(h01),
                                               v.y - __high2float(h01));
    __nv_bfloat162 l23 = __floats2bfloat162_rn(v.z - __low2float(h23),
                                               v.w - __high2float(h23));
    hi = make_uint2(bits2(h01), bits2(h23));
    lo = make_uint2(bits2(l01), bits2(l23));
}
__device__ __forceinline__ void split2(float a, float b, uint32_t& hi, uint32_t& lo) {
    __nv_bfloat162 h = __floats2bfloat162_rn(a, b);
    __nv_bfloat162 l = __floats2bfloat162_rn(a - __low2float(h), b - __high2float(h));
    hi = bits2(h);
    lo = bits2(l);
}

// ---------------- bf16x3 mma.sync GEMM (identical to R15, passing) -----------
#define BK 32
#define SSTR 40
#define T_HI (128 * SSTR * 2)      /* 10240 */
#define OFF_AL T_HI
#define OFF_BH (2 * T_HI)
#define OFF_BL (3 * T_HI)
#define BUF_B  (4 * T_HI)          /* 40960 */
#define GSMEM_BYTES (2 * BUF_B)    /* 81920 */
#define NCHUNK (CDIM / BK)         /* 24 */

template <int MODE>
__global__ void __launch_bounds__(128) tcgemm(const float* __restrict__ A,
                                              const float* __restrict__ Bw,
                                              const float* __restrict__ bias,
                                              float* __restrict__ Cout) {
    extern __shared__ __align__(128) char smem[];
    const int tid = threadIdx.x;
    const int wid = tid >> 5, lane = tid & 31;
    const int m0w = (wid >> 1) * 64;
    const int n0w = (wid & 1) * 64;
    const int rowBase = blockIdx.y * 128;
    const int colBase = blockIdx.x * 128;
    const float* Asrc = (MODE == 1) ? (const float*)g_O : A;
    const uint32_t sbase = smem_u32(smem);

    const int sr = tid >> 3;
    const int sc = (tid & 7) * 4;

    float4 aR[8];
    auto ldgA = [&](int k0) {
#pragma unroll
        for (int u = 0; u < 8; u++) {
            int r = u * 16 + sr;
            aR[u] = *reinterpret_cast<const float4*>(
                Asrc + (size_t)(rowBase + r) * CDIM + k0 + sc);
        }
    };

    float acc[4][8][4] = {};
    ldgA(0);

    for (int c = 0; c < NCHUNK; c++) {
        char* bufp = smem + (c & 1) * BUF_B;
        const uint32_t bufu = sbase + (uint32_t)(c & 1) * BUF_B;
        const int k0 = c * BK;

#pragma unroll
        for (int u = 0; u < 8; u++) {
            int r = u * 16 + sr;
            uint32_t off = (uint32_t)(r * SSTR + sc) * 2;
            uint2 hi, lo;
            split4(aR[u], hi, lo);
            *reinterpret_cast<uint2*>(bufp + off) = hi;
            *reinterpret_cast<uint2*>(bufp + OFF_AL + off) = lo;
        }
#pragma unroll
        for (int u = 0; u < 8; u++) {
            int r = u * 16 + sr;
            float4 v = *reinterpret_cast<const float4*>(
                Bw + (size_t)(colBase + r) * CDIM + k0 + sc);
            uint32_t off = (uint32_t)(r * SSTR + sc) * 2;
            uint2 hi, lo;
            split4(v, hi, lo);
            *reinterpret_cast<uint2*>(bufp + OFF_BH + off) = hi;
            *reinterpret_cast<uint2*>(bufp + OFF_BL + off) = lo;
        }
        __syncthreads();

        if (c + 1 < NCHUNK) ldgA((c + 1) * BK);

#pragma unroll
        for (int ks = 0; ks < 2; ks++) {
            const int k16 = ks * 16;
            uint32_t aHi[4][4], aLo[4][4], bHi[4][4], bLo[4][4];

            uint32_t aoff =
                bufu + (uint32_t)((m0w + (lane & 15)) * SSTR + k16 + (lane >> 4) * 8) * 2;
#pragma unroll
            for (int mi = 0; mi < 4; mi++) {
                ldsm4(aHi[mi], aoff + mi * (16 * SSTR * 2));
                ldsm4(aLo[mi], aoff + OFF_AL + mi * (16 * SSTR * 2));
            }
            {
                int g = lane >> 3, w8 = lane & 7;
                uint32_t boff = bufu + OFF_BH +
                                (uint32_t)((n0w + (g >> 1) * 8 + w8) * SSTR + k16 +
                                           (g & 1) * 8) * 2;
#pragma unroll
                for (int np = 0; np < 4; np++) {
                    ldsm4(bHi[np], boff + np * (16 * SSTR * 2));
                    ldsm4(bLo[np], boff + T_HI + np * (16 * SSTR * 2));
                }
            }
#pragma unroll
            for (int mi = 0; mi < 4; mi++)
#pragma unroll
                for (int ni = 0; ni < 8; ni++)
                    mma16816(acc[mi][ni], aHi[mi], &bHi[ni >> 1][(ni & 1) * 2]);
#pragma unroll
            for (int mi = 0; mi < 4; mi++)
#pragma unroll
                for (int ni = 0; ni < 8; ni++)
                    mma16816(acc[mi][ni], aHi[mi], &bLo[ni >> 1][(ni & 1) * 2]);
#pragma unroll
            for (int mi = 0; mi < 4; mi++)
#pragma unroll
                for (int ni = 0; ni < 8; ni++)
                    mma16816(acc[mi][ni], aLo[mi], &bHi[ni >> 1][(ni & 1) * 2]);
        }
        __syncthreads();
    }

#pragma unroll
    for (int mi = 0; mi < 4; mi++) {
        int m = rowBase + m0w + 16 * mi + (lane >> 2);
#pragma unroll
        for (int ni = 0; ni < 8; ni++) {
            int e = colBase + n0w + 8 * ni + (lane & 3) * 2;
            float2 v0 = make_float2(acc[mi][ni][0], acc[mi][ni][1]);
            float2 v1 = make_float2(acc[mi][ni][2], acc[mi][ni][3]);
            if (MODE == 0) {
                int tsel = e / CDIM;
                int rr = e - tsel * CDIM;
                int h = rr >> 6, d = rr & 63;
                float* dst = (tsel == 0) ? g_Q : ((tsel == 1) ? g_K : g_V);
                int bb = m >> 11, n = m & (NTOK - 1);
                size_t base = ((size_t)(bb * HEADS + h)) * NTOK;
                *reinterpret_cast<float2*>(&dst[(base + n) * DHEAD + d]) = v0;
                *reinterpret_cast<float2*>(&dst[(base + n + 8) * DHEAD + d]) = v1;
            } else {
                float2 bv = *reinterpret_cast<const float2*>(&bias[e]);
                v0.x += bv.x; v0.y += bv.y;
                v1.x += bv.x; v1.y += bv.y;
                *reinterpret_cast<float2*>(&Cout[(size_t)m * CDIM + e]) = v0;
                *reinterpret_cast<float2*>(&Cout[(size_t)(m + 8) * CDIM + e]) = v1;
            }
        }
    }
}

// ---------------- Sliding-window attention, bf16x3 mma.sync ------------------
// Smem time-multiplexed to fit 2 CTAs/SM (102400 B):
//  phase 1 (stage + QK^T): Qh 0..9216, Ql 9216..18432, Kh 18432..46080,
//                          Kl 46080..73728
//  phase 2 (S):            S fp32 at 0..50176 (overlays dead Q/K head)
//  phase 3 (P + VT):       Ph 51200..76800, Pl 76800..102400;
//                          VT built from gmem V reload (L2-hot) at 0..51200,
//                          overlaying dead S.
#define KSLOTS 192
#define QSTR 72
#define KSTR 72
#define PSTR 200
#define VSTR 200
#define SSTRIDE 196
#define OFF_QH 0
#define OFF_QL 9216
#define OFF_KH 18432
#define OFF_KL 46080
#define OFF_S  0
#define OFF_PH 51200
#define OFF_PL 76800
#define OFF_VTH 0
#define OFF_VTL 25600
#define ATT_SMEM 102400

__global__ void __launch_bounds__(256, 2) attn_mma() {
    extern __shared__ __align__(128) char sm[];
    const uint32_t sb = smem_u32(sm);
    const int tid = threadIdx.x;
    const int wid = tid >> 5, lane = tid & 31;
    const int q0 = blockIdx.x * 64;
    const int bh = blockIdx.y;
    const int kstart = q0 - HALF;

    const float* Qg = g_Q + (size_t)bh * NTOK * DHEAD;
    const float* Kg = g_K + (size_t)bh * NTOK * DHEAD;
    const float* Vg = g_V + (size_t)bh * NTOK * DHEAD;

    // ---- phase 1: stage Q and K only ----
    for (int idx = tid; idx < 64 * 16; idx += 256) {
        int q = idx >> 4, d4 = (idx & 15) << 2;
        float4 v = *reinterpret_cast<const float4*>(&Qg[(size_t)(q0 + q) * DHEAD + d4]);
        uint2 hi, lo;
        split4(v, hi, lo);
        uint32_t off = (uint32_t)(q * QSTR + d4) * 2;
        *reinterpret_cast<uint2*>(sm + OFF_QH + off) = hi;
        *reinterpret_cast<uint2*>(sm + OFF_QL + off) = lo;
    }
    for (int idx = tid; idx < KSLOTS * 16; idx += 256) {
        int s = idx >> 4, d4 = (idx & 15) << 2;
        int j = kstart + s;
        float4 kv = make_float4(0.f, 0.f, 0.f, 0.f);
        if (j >= 0 && j < NTOK)
            kv = *reinterpret_cast<const float4*>(&Kg[(size_t)j * DHEAD + d4]);
        uint2 hi, lo;
        split4(kv, hi, lo);
        uint32_t off = (uint32_t)(s * KSTR + d4) * 2;
        *reinterpret_cast<uint2*>(sm + OFF_KH + off) = hi;
        *reinterpret_cast<uint2*>(sm + OFF_KL + off) = lo;
    }
    __syncthreads();

    // ---- QK^T: warp grid 2x4 (m 2x32, n 4x48) ----
    const int wm = (wid >> 2) * 32;
    const int wn = (wid & 3) * 48;
    float sacc[2][6][4] = {};
    {
        const int g = lane >> 3, w8 = lane & 7;
#pragma unroll
        for (int ks = 0; ks < 4; ks++) {
            const int k16 = ks * 16;
            uint32_t qh[2][4], ql[2][4], kh[3][4], kl[3][4];
            uint32_t aoff = sb + OFF_QH +
                (uint32_t)((wm + (lane & 15)) * QSTR + k16 + (lane >> 4) * 8) * 2;
#pragma unroll
            for (int mi = 0; mi < 2; mi++) {
                ldsm4(qh[mi], aoff + mi * (16 * QSTR * 2));
                ldsm4(ql[mi], aoff + (OFF_QL - OFF_QH) + mi * (16 * QSTR * 2));
            }
            uint32_t boff = sb + OFF_KH +
                (uint32_t)((wn + (g >> 1) * 8 + w8) * KSTR + k16 + (g & 1) * 8) * 2;
#pragma unroll
            for (int np = 0; np < 3; np++) {
                ldsm4(kh[np], boff + np * (16 * KSTR * 2));
                ldsm4(kl[np], boff + (OFF_KL - OFF_KH) + np * (16 * KSTR * 2));
            }
#pragma unroll
            for (int mi = 0; mi < 2; mi++)
#pragma unroll
                for (int nt = 0; nt < 6; nt++)
                    mma16816(sacc[mi][nt], qh[mi], &kh[nt >> 1][(nt & 1) * 2]);
#pragma unroll
            for (int mi = 0; mi < 2; mi++)
#pragma unroll
                for (int nt = 0; nt < 6; nt++)
                    mma16816(sacc[mi][nt], qh[mi], &kl[nt >> 1][(nt & 1) * 2]);
#pragma unroll
            for (int mi = 0; mi < 2; mi++)
#pragma unroll
                for (int nt = 0; nt < 6; nt++)
                    mma16816(sacc[mi][nt], ql[mi], &kh[nt >> 1][(nt & 1) * 2]);
        }
    }
    __syncthreads();  // Q/K reads done; region becomes S

    // ---- scale + mask, write S fp32 (at offset 0, over dead Q/K) ----
    float* S = (float*)(sm + OFF_S);
#pragma unroll
    for (int mi = 0; mi < 2; mi++) {
        int qA = wm + 16 * mi + (lane >> 2);
#pragma unroll
        for (int nt = 0; nt < 6; nt++) {
            int s0 = wn + 8 * nt + (lane & 3) * 2;
#pragma unroll
            for (int half = 0; half < 2; half++) {
                int q = qA + half * 8;
#pragma unroll
                for (int e = 0; e < 2; e++) {
                    int s = s0 + e;
                    int kj = kstart + s;
                    int diff = q + HALF - s;
                    bool ok = (kj >= 0) & (kj < NTOK) & (diff >= -HALF) & (diff <= HALF);
                    S[q * SSTRIDE + s] =
                        ok ? sacc[mi][nt][half * 2 + e] * SCALE : -3.0e38f;
                }
            }
        }
    }
    __syncthreads();

    // ---- softmax (S -> registers), then P stores + VT build concurrently ----
    {
        const int row = tid >> 2, part = tid & 3;
        const float* srow = S + row * SSTRIDE + part * 48;
        float vals[48];
#pragma unroll
        for (int i = 0; i < 12; i++) {
            float4 v = *reinterpret_cast<const float4*>(srow + 4 * i);
            vals[4 * i] = v.x; vals[4 * i + 1] = v.y;
            vals[4 * i + 2] = v.z; vals[4 * i + 3] = v.w;
        }
        float mx = -3.0e38f;
#pragma unroll
        for (int i = 0; i < 48; i++) mx = fmaxf(mx, vals[i]);
        mx = fmaxf(mx, __shfl_xor_sync(0xffffffff, mx, 1));
        mx = fmaxf(mx, __shfl_xor_sync(0xffffffff, mx, 2));
        float sum = 0.f;
#pragma unroll
        for (int i = 0; i < 48; i++) {
            vals[i] = __expf(vals[i] - mx);
            sum += vals[i];
        }
        sum += __shfl_xor_sync(0xffffffff, sum, 1);
        sum += __shfl_xor_sync(0xffffffff, sum, 2);
        float inv = __fdividef(1.f, sum);
        __syncthreads();  // all S reads complete; S region becomes VT
        uint32_t pbase = (uint32_t)(row * PSTR + part * 48) * 2;
#pragma unroll
        for (int i = 0; i < 24; i++) {
            uint32_t h, l;
            split2(vals[2 * i] * inv, vals[2 * i + 1] * inv, h, l);
            *reinterpret_cast<uint32_t*>(sm + OFF_PH + pbase + 4 * i) = h;
            *reinterpret_cast<uint32_t*>(sm + OFF_PL + pbase + 4 * i) = l;
        }
    }
    // VT build: reload V from gmem (L2-hot), split, store transposed
    for (int idx = tid; idx < KSLOTS * 16; idx += 256) {
        int s = idx >> 4, d4 = (idx & 15) << 2;
        int j = kstart + s;
        float4 vv = make_float4(0.f, 0.f, 0.f, 0.f);
        if (j >= 0 && j < NTOK)
            vv = *reinterpret_cast<const float4*>(&Vg[(size_t)j * DHEAD + d4]);
        float vf[4] = {vv.x, vv.y, vv.z, vv.w};
#pragma unroll
        for (int i = 0; i < 4; i++) {
            __nv_bfloat16 h = __float2bfloat16_rn(vf[i]);
            __nv_bfloat16 l = __float2bfloat16_rn(vf[i] - __bfloat162float(h));
            ((__nv_bfloat16*)(sm + OFF_VTH))[(d4 + i) * VSTR + s] = h;
            ((__nv_bfloat16*)(sm + OFF_VTL))[(d4 + i) * VSTR + s] = l;
        }
    }
    __syncthreads();

    // ---- PV: warp grid 2x4 (m 2x32, n(d) 4x16) ----
    const int wn2 = (wid & 3) * 16;
    float facc[2][2][4] = {};
    {
        const int g = lane >> 3, w8 = lane & 7;
#pragma unroll
        for (int ks = 0; ks < 12; ks++) {
            const int k16 = ks * 16;
            uint32_t ph[2][4], pl[2][4], vh[4], vl[4];
            uint32_t aoff = sb + OFF_PH +
                (uint32_t)((wm + (lane & 15)) * PSTR + k16 + (lane >> 4) * 8) * 2;
#pragma unroll
            for (int mi = 0; mi < 2; mi++) {
                ldsm4(ph[mi], aoff + mi * (16 * PSTR * 2));
                ldsm4(pl[mi], aoff + (OFF_PL - OFF_PH) + mi * (16 * PSTR * 2));
            }
            uint32_t boff = sb + OFF_VTH +
                (uint32_t)((wn2 + (g >> 1) * 8 + w8) * VSTR + k16 + (g & 1) * 8) * 2;
            ldsm4(vh, boff);
            ldsm4(vl, boff + (OFF_VTL - OFF_VTH));
#pragma unroll
            for (int mi = 0; mi < 2; mi++)
#pragma unroll
                for (int nt = 0; nt < 2; nt++)
                    mma16816(facc[mi][nt], ph[mi], &vh[nt * 2]);
#pragma unroll
            for (int mi = 0; mi < 2; mi++)
#pragma unroll
                for (int nt = 0; nt < 2; nt++)
                    mma16816(facc[mi][nt], ph[mi], &vl[nt * 2]);
#pragma unroll
            for (int mi = 0; mi < 2; mi++)
#pragma unroll
                for (int nt = 0; nt < 2; nt++)
                    mma16816(facc[mi][nt], pl[mi], &vh[nt * 2]);
        }
    }

    // ---- epilogue -> g_O [B,N,C] ----
    const int b = bh / HEADS, h = bh - b * HEADS;
#pragma unroll
    for (int mi = 0; mi < 2; mi++) {
        int n = q0 + wm + 16 * mi + (lane >> 2);
#pragma unroll
        for (int nt = 0; nt < 2; nt++) {
            int d = wn2 + 8 * nt + (lane & 3) * 2;
            float* p0 = &g_O[((size_t)b * NTOK + n) * CDIM + h * DHEAD + d];
            float* p1 = &g_O[((size_t)b * NTOK + n + 8) * CDIM + h * DHEAD + d];
            *reinterpret_cast<float2*>(p0) = make_float2(facc[mi][nt][0], facc[mi][nt][1]);
            *reinterpret_cast<float2*>(p1) = make_float2(facc[mi][nt][2], facc[mi][nt][3]);
        }
    }
}

// ---------------- launch ----------------------------------------------------
extern "C" void kernel_launch(void* const* d_in, const int* in_sizes, int n_in,
                              void* d_out, int out_size) {
    (void)in_sizes; (void)n_in; (void)out_size;
    const float* x      = (const float*)d_in[0];
    const float* w_qkv  = (const float*)d_in[1];
    const float* w_proj = (const float*)d_in[2];
    const float* b_proj = (const float*)d_in[3];
    float* out = (float*)d_out;

    cudaFuncSetAttribute(tcgemm<0>, cudaFuncAttributeMaxDynamicSharedMemorySize,
                         GSMEM_BYTES);
    cudaFuncSetAttribute(tcgemm<1>, cudaFuncAttributeMaxDynamicSharedMemorySize,
                         GSMEM_BYTES);
    cudaFuncSetAttribute(attn_mma, cudaFuncAttributeMaxDynamicSharedMemorySize,
                         ATT_SMEM);

    // 1) QKV projection (bf16x3 mma.sync, 128x128 tiles, 64x64 warp tiles)
    tcgemm<0><<<dim3(3 * CDIM / 128, BATCH * NTOK / 128), 128, GSMEM_BYTES>>>(
        x, w_qkv, nullptr, nullptr);

    // 2) Sliding-window attention (2 CTAs/SM via smem time-multiplexing)
    attn_mma<<<dim3(NTOK / 64, BATCH * HEADS), 256, ATT_SMEM>>>();

    // 3) Output projection + bias -> d_out
    tcgemm<1><<<dim3(CDIM / 128, BATCH * NTOK / 128), 128, GSMEM_BYTES>>>(
        nullptr, w_proj, b_proj, out);
}